// round 10
// baseline (speedup 1.0000x reference)
#include <cuda_runtime.h>
#include <cstdint>

// Problem constants
#define DN   16384
#define DD   128
#define DM1  64
#define DKK  8
#define NPC  8          // nodes per CTA
#define ROWTILE 256     // rows per CTA
#define THREADS 512     // 16 warps: 8 row-groups (32 rows) x 2 n-halves (32 cols)

// ---------------- device scratch (static, no allocs) ----------------
__device__ __align__(128) float g_Wc[DD * DM1 * DD];
__device__ __align__(128) float g_Xc[DN * DD];
__device__ float g_weffh[DD * DM1];   // 0.5 * weff
__device__ float g_beffh[DD * DM1];   // 0.5 * beff
__device__ float g_ceff2[DD];         // ceff + 0.5 * sum_m weff

// 16-col-group permutation: thread tg's frags for chunk pair (2c,2c+1) are
// the 16B at float offset 16c + 4*tg
__host__ __device__ __forceinline__ int perm16(int k) {
    return (k & ~15) | ((k & 3) << 2) | ((k >> 2) & 3);
}

__device__ __forceinline__ float to_tf32(float v) {
    uint32_t t;
    asm("cvt.rna.tf32.f32 %0, %1;" : "=r"(t) : "f"(v));
    return __uint_as_float(t);
}

__device__ __forceinline__ uint32_t smem_u32(const void* p) {
    uint32_t a;
    asm("{ .reg .u64 t; cvta.to.shared.u64 t, %1; cvt.u32.u64 %0, t; }" : "=r"(a) : "l"(p));
    return a;
}

__device__ __forceinline__ float tanha(float x) {
    float r;
    asm("tanh.approx.f32 %0, %1;" : "=f"(r) : "f"(x));
    return r;
}

__device__ __forceinline__ void mma_tf32(float* c, uint32_t a0, uint32_t a1, uint32_t a2,
                                         uint32_t a3, uint32_t b0, uint32_t b1) {
    asm volatile(
        "mma.sync.aligned.m16n8k8.row.col.f32.tf32.tf32.f32 "
        "{%0,%1,%2,%3}, {%4,%5,%6,%7}, {%8,%9}, {%0,%1,%2,%3};"
        : "+f"(c[0]), "+f"(c[1]), "+f"(c[2]), "+f"(c[3])
        : "r"(a0), "r"(a1), "r"(a2), "r"(a3), "r"(b0), "r"(b1));
}

__device__ __forceinline__ void cp16(uint32_t dst, const void* src) {
    asm volatile("cp.async.cg.shared.global [%0], [%1], 16;" :: "r"(dst), "l"(src) : "memory");
}
#define CP_COMMIT() asm volatile("cp.async.commit_group;" ::: "memory")
#define CP_WAIT0()  asm volatile("cp.async.wait_group 0;" ::: "memory")

// ---------------- precompute kernels ----------------
__global__ void prep_meta_kernel(const float* __restrict__ w2, const float* __restrict__ b2,
                                 const float* __restrict__ w3, const float* __restrict__ b1p,
                                 const float* __restrict__ b1n) {
    __shared__ float sw[DM1];
    int j = blockIdx.x;
    int m = threadIdx.x;
    float acc = 0.f;
#pragma unroll
    for (int k = 0; k < DKK; k++) acc += w3[j * DKK + k] * w2[k * DM1 + m];
    sw[m] = acc;
    g_weffh[j * DM1 + m] = 0.5f * acc;
    g_beffh[j * DM1 + m] = 0.5f * (b1p[j * DM1 + m] - b1n[j * DM1 + m]);
    __syncthreads();
    if (m == 0) {
        float c = 0.f;
#pragma unroll
        for (int k = 0; k < DKK; k++) c += w3[j * DKK + k] * b2[k];
        float s = 0.f;
#pragma unroll
        for (int t = 0; t < DM1; t++) s += sw[t];
        g_ceff2[j] = c + 0.5f * s;
    }
}

__global__ void prep_w_kernel(const float* __restrict__ w1p, const float* __restrict__ w1n) {
    int j = blockIdx.x;
    const float* p = w1p + (size_t)j * (DM1 * DD);
    const float* q = w1n + (size_t)j * (DM1 * DD);
    float* dst = g_Wc + (size_t)j * (DM1 * DD);
    for (int e = threadIdx.x; e < DM1 * DD; e += blockDim.x) {
        int m = e >> 7, k = e & 127;
        float v = p[e] - q[e];
        if (k == j) v = 0.f;
        dst[m * DD + perm16(k)] = to_tf32(v);
    }
}

__global__ void prep_x_kernel(const float* __restrict__ x) {
    size_t base = (size_t)blockIdx.x * (size_t)(128 * DD);
    const float* src = x + base;
    float* dst = g_Xc + base;
    for (int e = threadIdx.x; e < 128 * DD; e += blockDim.x) {
        int r = e >> 7, k = e & 127;
        dst[r * DD + perm16(k)] = to_tf32(src[e]);
    }
}

// ---------------- main fused kernel ----------------
// SMEM (floats), row stride 144 (576B ≡ 64 mod 128 -> LDS.128 4-phase conflict-free)
#define XSTR 144
#define XO   0                          // X: 256 x 144 = 36864 floats
#define WO   36864                      // W: 2 bufs x (64 x 144) = 18432
#define WBUF 9216
#define MBo  55296                      // 0.5*beff 8x64 = 512
#define MWo  55808                      // 0.5*weff 8x64 = 512
#define MCo  56320                      // ceff' 8
#define OTo  56328                      // partial ring: 2 slots x (256 rows x 2 halves) = 2x512
#define OSLOT 512
#define SMEM_FLOATS 57352
#define SMEM_BYTES  (SMEM_FLOATS * 4)   // 229408

__device__ __forceinline__ void load_w_tile(uint32_t sb, int buf, int j, int tid) {
    const float4* src = (const float4*)(g_Wc + (size_t)j * (DM1 * DD));
#pragma unroll
    for (int e = tid; e < 2048; e += THREADS) {
        int m = e >> 5, c = e & 31;
        uint32_t dst = sb + (uint32_t)(WO * 4 + buf * (WBUF * 4) + m * (XSTR * 4) + c * 16);
        cp16(dst, src + e);
    }
}

// MMA one node: warp = 32 rows (2 m-tiles) x 32 cols (4 n-tiles). acc[mt][nt][quad]
__device__ __forceinline__ void mma_node(const float* Wb,
                                         const float* Xm0r0, const float* Xm0r1,
                                         const float* Xm1r0, const float* Xm1r1,
                                         int g, int tg, float acc[2][4][4]) {
#pragma unroll
    for (int mt = 0; mt < 2; mt++)
#pragma unroll
        for (int nt = 0; nt < 4; nt++)
#pragma unroll
            for (int q = 0; q < 4; q++) acc[mt][nt][q] = 0.f;

#pragma unroll
    for (int c = 0; c < 8; c++) {            // kt-pair: chunks 2c, 2c+1
        const int off = c * 16 + 4 * tg;
        float4 a00 = *(const float4*)(Xm0r0 + off);
        float4 a01 = *(const float4*)(Xm0r1 + off);
        float4 a10 = *(const float4*)(Xm1r0 + off);
        float4 a11 = *(const float4*)(Xm1r1 + off);
#pragma unroll
        for (int nt = 0; nt < 4; nt++) {
            float4 b = *(const float4*)(Wb + (nt * 8 + g) * XSTR + off);
            uint32_t bx = __float_as_uint(b.x), by = __float_as_uint(b.y);
            uint32_t bz = __float_as_uint(b.z), bw = __float_as_uint(b.w);
            mma_tf32(acc[0][nt], __float_as_uint(a00.x), __float_as_uint(a01.x),
                     __float_as_uint(a00.y), __float_as_uint(a01.y), bx, by);
            mma_tf32(acc[1][nt], __float_as_uint(a10.x), __float_as_uint(a11.x),
                     __float_as_uint(a10.y), __float_as_uint(a11.y), bx, by);
            mma_tf32(acc[0][nt], __float_as_uint(a00.z), __float_as_uint(a01.z),
                     __float_as_uint(a00.w), __float_as_uint(a01.w), bz, bw);
            mma_tf32(acc[1][nt], __float_as_uint(a10.z), __float_as_uint(a11.z),
                     __float_as_uint(a10.w), __float_as_uint(a11.w), bz, bw);
        }
    }
}

// epilogue node jj: partial over this warp's 32 n-cols -> ring slot jj&1
// slot layout: [row*2 + nh], row in 0..255
__device__ __forceinline__ void epi_node(float* sm, const float acc[2][4][4],
                                         int jj, int nbase, int rbase, int nh, int g, int tg) {
    const float* mb = sm + MBo + jj * DM1 + nbase;
    const float* mw = sm + MWo + jj * DM1 + nbase;
    float p00 = 0.f, p01 = 0.f, p10 = 0.f, p11 = 0.f;
#pragma unroll
    for (int nt = 0; nt < 4; nt++) {
        int c0 = nt * 8 + 2 * tg;
        float2 w2v = *(const float2*)(mw + c0);
        float2 b2v = *(const float2*)(mb + c0);
        p00 += w2v.x * tanha(fmaf(acc[0][nt][0], 0.5f, b2v.x))
             + w2v.y * tanha(fmaf(acc[0][nt][1], 0.5f, b2v.y));
        p01 += w2v.x * tanha(fmaf(acc[0][nt][2], 0.5f, b2v.x))
             + w2v.y * tanha(fmaf(acc[0][nt][3], 0.5f, b2v.y));
        p10 += w2v.x * tanha(fmaf(acc[1][nt][0], 0.5f, b2v.x))
             + w2v.y * tanha(fmaf(acc[1][nt][1], 0.5f, b2v.y));
        p11 += w2v.x * tanha(fmaf(acc[1][nt][2], 0.5f, b2v.x))
             + w2v.y * tanha(fmaf(acc[1][nt][3], 0.5f, b2v.y));
    }
    p00 += __shfl_xor_sync(0xFFFFFFFFu, p00, 1);
    p00 += __shfl_xor_sync(0xFFFFFFFFu, p00, 2);
    p01 += __shfl_xor_sync(0xFFFFFFFFu, p01, 1);
    p01 += __shfl_xor_sync(0xFFFFFFFFu, p01, 2);
    p10 += __shfl_xor_sync(0xFFFFFFFFu, p10, 1);
    p10 += __shfl_xor_sync(0xFFFFFFFFu, p10, 2);
    p11 += __shfl_xor_sync(0xFFFFFFFFu, p11, 1);
    p11 += __shfl_xor_sync(0xFFFFFFFFu, p11, 2);
    if (tg == 0) {
        float* o = sm + OTo + (jj & 1) * OSLOT + (rbase + g) * 2 + nh;
        o[0]  = p00;          // row rbase+g
        o[16] = p01;          // row rbase+g+8   (+8 rows * 2 floats)
        o[32] = p10;          // row rbase+g+16
        o[48] = p11;          // row rbase+g+24
    }
}

// combine node jj partials (call right after a __syncthreads covering the epi STS)
__device__ __forceinline__ void combine_node(const float* sm, float* __restrict__ out,
                                             int jj, int jbase, int tileR, int tid) {
    if (tid < ROWTILE) {
        float2 v = *(const float2*)(sm + OTo + (jj & 1) * OSLOT + tid * 2);
        out[((size_t)tileR * ROWTILE + tid) * DD + jbase + jj] = v.x + v.y + sm[MCo + jj];
    }
}

__global__ void __launch_bounds__(THREADS, 1)
fused_dag_kernel(float* __restrict__ out) {
    extern __shared__ float sm[];
    const uint32_t sb = smem_u32(sm);
    const int tid = threadIdx.x;
    const int w = tid >> 5;
    const int lane = tid & 31;
    const int g = lane >> 2;
    const int tg = lane & 3;
    const int mg = w >> 1;                 // 0..7 : rows mg*32..mg*32+31
    const int nh = w & 1;                  // 0..1 : cols nh*32..nh*32+31
    const int tileR = blockIdx.x;          // 0..63
    const int jbase = blockIdx.y * NPC;

    // ---- async loads: X tile + W buf0 ----
    {
        const float4* src = (const float4*)(g_Xc + (size_t)tileR * (ROWTILE * DD));
#pragma unroll
        for (int e = tid; e < 8192; e += THREADS) {
            int r = e >> 5, c = e & 31;
            uint32_t dst = sb + (uint32_t)(r * (XSTR * 4) + c * 16);
            cp16(dst, src + e);
        }
    }
    load_w_tile(sb, 0, jbase, tid);
    CP_COMMIT();

    // ---- meta into smem ----
    if (tid < NPC * DM1) {
        int jj = tid >> 6, m = tid & 63;
        int j = jbase + jj;
        sm[MBo + tid] = g_beffh[j * DM1 + m];
        sm[MWo + tid] = g_weffh[j * DM1 + m];
    }
    if (tid < NPC) sm[MCo + tid] = g_ceff2[jbase + tid];

    const int rbase = mg * 32;
    const float* Xm0r0 = sm + (rbase + g) * XSTR;
    const float* Xm0r1 = Xm0r0 + 8 * XSTR;
    const float* Xm1r0 = Xm0r0 + 16 * XSTR;
    const float* Xm1r1 = Xm0r0 + 24 * XSTR;
    const int nbase = nh * 32;
    const float* Wb0 = sm + WO + nbase * XSTR;
    const float* Wb1 = sm + WO + WBUF + nbase * XSTR;

    // STATIC accumulator sets (compile-time indexing only)
    float accA[2][4][4];   // even nodes
    float accB[2][4][4];   // odd nodes

#pragma unroll 1
    for (int ii = 0; ii < NPC; ii += 2) {
        // ---- node ii (even, buf0 -> accA) ----
        CP_WAIT0();
        __syncthreads();
        if (ii >= 2) combine_node(sm, out, ii - 2, jbase, tileR, tid);
        if (ii + 1 < NPC) { load_w_tile(sb, 1, jbase + ii + 1, tid); CP_COMMIT(); }
        mma_node(Wb0, Xm0r0, Xm0r1, Xm1r0, Xm1r1, g, tg, accA);
        if (ii > 0) epi_node(sm, accB, ii - 1, nbase, rbase, nh, g, tg);

        // ---- node ii+1 (odd, buf1 -> accB) ----
        CP_WAIT0();
        __syncthreads();
        if (ii >= 2) combine_node(sm, out, ii - 1, jbase, tileR, tid);
        if (ii + 2 < NPC) { load_w_tile(sb, 0, jbase + ii + 2, tid); CP_COMMIT(); }
        mma_node(Wb1, Xm0r0, Xm0r1, Xm1r0, Xm1r1, g, tg, accB);
        epi_node(sm, accA, ii, nbase, rbase, nh, g, tg);
    }
    // tail: epi for node 7, then combine 6 and 7
    epi_node(sm, accB, NPC - 1, nbase, rbase, nh, g, tg);
    __syncthreads();
    combine_node(sm, out, NPC - 2, jbase, tileR, tid);
    combine_node(sm, out, NPC - 1, jbase, tileR, tid);
}

// ---------------- launch ----------------
extern "C" void kernel_launch(void* const* d_in, const int* in_sizes, int n_in,
                              void* d_out, int out_size) {
    const float* x   = (const float*)d_in[0];
    const float* w1p = (const float*)d_in[1];
    const float* b1p = (const float*)d_in[2];
    const float* w1n = (const float*)d_in[3];
    const float* b1n = (const float*)d_in[4];
    const float* w2  = (const float*)d_in[5];
    const float* b2  = (const float*)d_in[6];
    const float* w3  = (const float*)d_in[7];
    float* out = (float*)d_out;

    prep_meta_kernel<<<DD, DM1>>>(w2, b2, w3, b1p, b1n);
    prep_w_kernel<<<DD, 256>>>(w1p, w1n);
    prep_x_kernel<<<DN / 128, 256>>>(x);

    cudaFuncSetAttribute(fused_dag_kernel, cudaFuncAttributeMaxDynamicSharedMemorySize,
                         SMEM_BYTES);
    dim3 grid(DN / ROWTILE, DD / NPC);
    fused_dag_kernel<<<grid, THREADS, SMEM_BYTES>>>(out);
}

// round 12
// speedup vs baseline: 1.2189x; 1.2189x over previous
#include <cuda_runtime.h>
#include <cstdint>

// Problem constants
#define DN   16384
#define DD   128
#define DM1  64
#define DKK  8
#define NPC  8          // nodes per CTA
#define ROWTILE 256     // rows per CTA
#define THREADS 256     // 8 warps; warp = 32 rows x 64 cols, A held in registers

// ---------------- device scratch (static, no allocs) ----------------
__device__ __align__(128) float g_Wc[DD * DM1 * DD];
__device__ __align__(128) float g_Xc[DN * DD];
__device__ float g_weffh[DD * DM1];   // 0.5 * weff
__device__ float g_beffh[DD * DM1];   // 0.5 * beff
__device__ float g_ceff2[DD];         // ceff + 0.5 * sum_m weff

// 16-col-group permutation: thread tg's frags for chunk pair (2c,2c+1) are
// the 16B at float offset 16c + 4*tg
__host__ __device__ __forceinline__ int perm16(int k) {
    return (k & ~15) | ((k & 3) << 2) | ((k >> 2) & 3);
}

__device__ __forceinline__ float to_tf32(float v) {
    uint32_t t;
    asm("cvt.rna.tf32.f32 %0, %1;" : "=r"(t) : "f"(v));
    return __uint_as_float(t);
}

__device__ __forceinline__ uint32_t smem_u32(const void* p) {
    uint32_t a;
    asm("{ .reg .u64 t; cvta.to.shared.u64 t, %1; cvt.u32.u64 %0, t; }" : "=r"(a) : "l"(p));
    return a;
}

__device__ __forceinline__ float tanha(float x) {
    float r;
    asm("tanh.approx.f32 %0, %1;" : "=f"(r) : "f"(x));
    return r;
}

__device__ __forceinline__ void mma_tf32(float* c, uint32_t a0, uint32_t a1, uint32_t a2,
                                         uint32_t a3, uint32_t b0, uint32_t b1) {
    asm volatile(
        "mma.sync.aligned.m16n8k8.row.col.f32.tf32.tf32.f32 "
        "{%0,%1,%2,%3}, {%4,%5,%6,%7}, {%8,%9}, {%0,%1,%2,%3};"
        : "+f"(c[0]), "+f"(c[1]), "+f"(c[2]), "+f"(c[3])
        : "r"(a0), "r"(a1), "r"(a2), "r"(a3), "r"(b0), "r"(b1));
}

__device__ __forceinline__ void cp16(uint32_t dst, const void* src) {
    asm volatile("cp.async.cg.shared.global [%0], [%1], 16;" :: "r"(dst), "l"(src) : "memory");
}
#define CP_COMMIT() asm volatile("cp.async.commit_group;" ::: "memory")
#define CP_WAIT0()  asm volatile("cp.async.wait_group 0;" ::: "memory")

// ---------------- precompute kernels ----------------
__global__ void prep_meta_kernel(const float* __restrict__ w2, const float* __restrict__ b2,
                                 const float* __restrict__ w3, const float* __restrict__ b1p,
                                 const float* __restrict__ b1n) {
    __shared__ float sw[DM1];
    int j = blockIdx.x;
    int m = threadIdx.x;
    float acc = 0.f;
#pragma unroll
    for (int k = 0; k < DKK; k++) acc += w3[j * DKK + k] * w2[k * DM1 + m];
    sw[m] = acc;
    g_weffh[j * DM1 + m] = 0.5f * acc;
    g_beffh[j * DM1 + m] = 0.5f * (b1p[j * DM1 + m] - b1n[j * DM1 + m]);
    __syncthreads();
    if (m == 0) {
        float c = 0.f;
#pragma unroll
        for (int k = 0; k < DKK; k++) c += w3[j * DKK + k] * b2[k];
        float s = 0.f;
#pragma unroll
        for (int t = 0; t < DM1; t++) s += sw[t];
        g_ceff2[j] = c + 0.5f * s;
    }
}

__global__ void prep_w_kernel(const float* __restrict__ w1p, const float* __restrict__ w1n) {
    int j = blockIdx.x;
    const float* p = w1p + (size_t)j * (DM1 * DD);
    const float* q = w1n + (size_t)j * (DM1 * DD);
    float* dst = g_Wc + (size_t)j * (DM1 * DD);
    for (int e = threadIdx.x; e < DM1 * DD; e += blockDim.x) {
        int m = e >> 7, k = e & 127;
        float v = p[e] - q[e];
        if (k == j) v = 0.f;
        dst[m * DD + perm16(k)] = to_tf32(v);
    }
}

__global__ void prep_x_kernel(const float* __restrict__ x) {
    size_t base = (size_t)blockIdx.x * (size_t)(128 * DD);
    const float* src = x + base;
    float* dst = g_Xc + base;
    for (int e = threadIdx.x; e < 128 * DD; e += blockDim.x) {
        int r = e >> 7, k = e & 127;
        dst[r * DD + perm16(k)] = to_tf32(src[e]);
    }
}

// ---------------- main fused kernel ----------------
// SMEM (floats), row stride 144 (576B ≡ 64 mod 128 -> LDS.128 4-phase conflict-free)
#define XSTR 144
#define XO   0                          // X: 256 x 144 = 36864 floats (read once into regs)
#define WO   36864                      // W: 2 bufs x (64 x 144) = 18432
#define WBUF 9216
#define MBo  55296                      // 0.5*beff 8x64 = 512
#define MWo  55808                      // 0.5*weff 8x64 = 512
#define MCo  56320                      // ceff' 8
#define SMEM_FLOATS 56328
#define SMEM_BYTES  (SMEM_FLOATS * 4)   // 225312

__device__ __forceinline__ void load_w_tile(uint32_t sb, int buf, int j, int tid) {
    const float4* src = (const float4*)(g_Wc + (size_t)j * (DM1 * DD));
#pragma unroll
    for (int e = tid; e < 2048; e += THREADS) {
        int m = e >> 5, c = e & 31;
        uint32_t dst = sb + (uint32_t)(WO * 4 + buf * (WBUF * 4) + m * (XSTR * 4) + c * 16);
        cp16(dst, src + e);
    }
}

__global__ void __launch_bounds__(THREADS, 1)
fused_dag_kernel(float* __restrict__ out) {
    extern __shared__ float sm[];
    const uint32_t sb = smem_u32(sm);
    const int tid = threadIdx.x;
    const int w = tid >> 5;                // 0..7 : rows w*32..w*32+31
    const int lane = tid & 31;
    const int g = lane >> 2;
    const int tg = lane & 3;
    const int tileR = blockIdx.x;          // 0..63
    const int jbase = blockIdx.y * NPC;

    // ---- async loads: X tile + W buf0 ----
    {
        const float4* src = (const float4*)(g_Xc + (size_t)tileR * (ROWTILE * DD));
#pragma unroll
        for (int e = tid; e < 8192; e += THREADS) {
            int r = e >> 5, c = e & 31;
            uint32_t dst = sb + (uint32_t)(r * (XSTR * 4) + c * 16);
            cp16(dst, src + e);
        }
    }
    load_w_tile(sb, 0, jbase, tid);
    CP_COMMIT();

    // ---- meta into smem ----
#pragma unroll
    for (int e = tid; e < NPC * DM1; e += THREADS) {
        int jj = e >> 6, m = e & 63;
        int j = jbase + jj;
        sm[MBo + e] = g_beffh[j * DM1 + m];
        sm[MWo + e] = g_weffh[j * DM1 + m];
    }
    if (tid < NPC) sm[MCo + tid] = g_ceff2[jbase + tid];

    const int rbase = w * 32;
    const float* Xm0r0 = sm + (rbase + g) * XSTR;
    const float* Xm0r1 = Xm0r0 + 8 * XSTR;
    const float* Xm1r0 = Xm0r0 + 16 * XSTR;
    const float* Xm1r1 = Xm0r0 + 24 * XSTR;
    const int rowg = tileR * ROWTILE + rbase + g;

    CP_WAIT0();
    __syncthreads();

    // ---- load ALL A fragments into registers ONCE (invariant across nodes) ----
    float4 Ar[8][4];
#pragma unroll
    for (int c = 0; c < 8; c++) {
        const int off = c * 16 + 4 * tg;
        Ar[c][0] = *(const float4*)(Xm0r0 + off);   // rows rbase+g     (chunks 2c,2c+1)
        Ar[c][1] = *(const float4*)(Xm0r1 + off);   // rows rbase+g+8
        Ar[c][2] = *(const float4*)(Xm1r0 + off);   // rows rbase+g+16
        Ar[c][3] = *(const float4*)(Xm1r1 + off);   // rows rbase+g+24
    }

#pragma unroll 1
    for (int i = 0; i < NPC; i++) {
        // buf[i&1] ready; all warps past node i-1's reads of buf[(i+1)&1]
        if (i > 0) {
            CP_WAIT0();
        }
        __syncthreads();
        if (i + 1 < NPC) { load_w_tile(sb, (i + 1) & 1, jbase + i + 1, tid); CP_COMMIT(); }

        const float* Wb = sm + WO + (i & 1) * WBUF;

        float acc[2][8][4];
#pragma unroll
        for (int mt = 0; mt < 2; mt++)
#pragma unroll
            for (int nt = 0; nt < 8; nt++)
#pragma unroll
                for (int q = 0; q < 4; q++) acc[mt][nt][q] = 0.f;

#pragma unroll
        for (int c = 0; c < 8; c++) {           // chunk pair 2c, 2c+1
            const int off = c * 16 + 4 * tg;
            const float4 a00 = Ar[c][0];
            const float4 a01 = Ar[c][1];
            const float4 a10 = Ar[c][2];
            const float4 a11 = Ar[c][3];
#pragma unroll
            for (int nt = 0; nt < 8; nt++) {
                float4 b = *(const float4*)(Wb + (nt * 8 + g) * XSTR + off);
                uint32_t bx = __float_as_uint(b.x), by = __float_as_uint(b.y);
                uint32_t bz = __float_as_uint(b.z), bw = __float_as_uint(b.w);
                mma_tf32(acc[0][nt], __float_as_uint(a00.x), __float_as_uint(a01.x),
                         __float_as_uint(a00.y), __float_as_uint(a01.y), bx, by);
                mma_tf32(acc[1][nt], __float_as_uint(a10.x), __float_as_uint(a11.x),
                         __float_as_uint(a10.y), __float_as_uint(a11.y), bx, by);
                mma_tf32(acc[0][nt], __float_as_uint(a00.z), __float_as_uint(a01.z),
                         __float_as_uint(a00.w), __float_as_uint(a01.w), bz, bw);
                mma_tf32(acc[1][nt], __float_as_uint(a10.z), __float_as_uint(a11.z),
                         __float_as_uint(a10.w), __float_as_uint(a11.w), bz, bw);
            }
        }

        // ---- epilogue: w*sig(h) = wh + wh*tanh(0.5h'); wh-sum folded into ceff' ----
        {
            const float* mb = sm + MBo + i * DM1;
            const float* mw = sm + MWo + i * DM1;
            float p00 = 0.f, p01 = 0.f, p10 = 0.f, p11 = 0.f;
#pragma unroll
            for (int nt = 0; nt < 8; nt++) {
                int c0 = nt * 8 + 2 * tg;
                float2 w2v = *(const float2*)(mw + c0);
                float2 b2v = *(const float2*)(mb + c0);
                p00 += w2v.x * tanha(fmaf(acc[0][nt][0], 0.5f, b2v.x))
                     + w2v.y * tanha(fmaf(acc[0][nt][1], 0.5f, b2v.y));
                p01 += w2v.x * tanha(fmaf(acc[0][nt][2], 0.5f, b2v.x))
                     + w2v.y * tanha(fmaf(acc[0][nt][3], 0.5f, b2v.y));
                p10 += w2v.x * tanha(fmaf(acc[1][nt][0], 0.5f, b2v.x))
                     + w2v.y * tanha(fmaf(acc[1][nt][1], 0.5f, b2v.y));
                p11 += w2v.x * tanha(fmaf(acc[1][nt][2], 0.5f, b2v.x))
                     + w2v.y * tanha(fmaf(acc[1][nt][3], 0.5f, b2v.y));
            }
            p00 += __shfl_xor_sync(0xFFFFFFFFu, p00, 1);
            p00 += __shfl_xor_sync(0xFFFFFFFFu, p00, 2);
            p01 += __shfl_xor_sync(0xFFFFFFFFu, p01, 1);
            p01 += __shfl_xor_sync(0xFFFFFFFFu, p01, 2);
            p10 += __shfl_xor_sync(0xFFFFFFFFu, p10, 1);
            p10 += __shfl_xor_sync(0xFFFFFFFFu, p10, 2);
            p11 += __shfl_xor_sync(0xFFFFFFFFu, p11, 1);
            p11 += __shfl_xor_sync(0xFFFFFFFFu, p11, 2);
            if (tg == 0) {
                float ce = sm[MCo + i];
                float* o = out + (size_t)rowg * DD + jbase + i;
                o[0 * DD]  = p00 + ce;
                o[8 * DD]  = p01 + ce;
                o[16 * DD] = p10 + ce;
                o[24 * DD] = p11 + ce;
            }
        }
    }
}

// ---------------- launch ----------------
extern "C" void kernel_launch(void* const* d_in, const int* in_sizes, int n_in,
                              void* d_out, int out_size) {
    const float* x   = (const float*)d_in[0];
    const float* w1p = (const float*)d_in[1];
    const float* b1p = (const float*)d_in[2];
    const float* w1n = (const float*)d_in[3];
    const float* b1n = (const float*)d_in[4];
    const float* w2  = (const float*)d_in[5];
    const float* b2  = (const float*)d_in[6];
    const float* w3  = (const float*)d_in[7];
    float* out = (float*)d_out;

    prep_meta_kernel<<<DD, DM1>>>(w2, b2, w3, b1p, b1n);
    prep_w_kernel<<<DD, 256>>>(w1p, w1n);
    prep_x_kernel<<<DN / 128, 256>>>(x);

    cudaFuncSetAttribute(fused_dag_kernel, cudaFuncAttributeMaxDynamicSharedMemorySize,
                         SMEM_BYTES);
    dim3 grid(DN / ROWTILE, DD / NPC);
    fused_dag_kernel<<<grid, THREADS, SMEM_BYTES>>>(out);
}